// round 6
// baseline (speedup 1.0000x reference)
#include <cuda_runtime.h>
#include <cstdint>
#include <cstddef>

// Problem constants
#define Bn 4
#define Cn 128
#define Hn 128
#define Wn 256
#define Dn 81
#define HWn (Hn * Wn)
#define TH 4        // output rows per block
#define TWt 128     // output cols per block
#define NTHREADS 384
#define CPS 4       // channels per pipeline stage
#define NSTG (Cn / CPS)   // 32 stages, double-buffered
#define X1P 132     // padded x1 row (floats)

// pack two float regs into an f32x2 operand
__device__ __forceinline__ double pkd(float a, float b) {
    double d;
    asm("mov.b64 %0, {%1, %2};" : "=d"(d) : "f"(a), "f"(b));
    return d;
}
__device__ __forceinline__ void fma2(double &d, double a, double b) {
    asm("fma.rn.f32x2 %0, %1, %2, %0;" : "+d"(d) : "d"(a), "d"(b));
}
__device__ __forceinline__ float dlo(double d) { return __int_as_float(__double2loint(d)); }
__device__ __forceinline__ float dhi(double d) { return __int_as_float(__double2hiint(d)); }
// cp.async 16B; src_sz=0 -> writes 16 zero bytes (halo fill)
__device__ __forceinline__ void cp16(void* dst_smem, const void* src, bool ok) {
    unsigned dst = (unsigned)__cvta_generic_to_shared(dst_smem);
    int sz = ok ? 16 : 0;
    asm volatile("cp.async.ca.shared.global [%0], [%1], 16, %2;" :: "r"(dst), "l"(src), "r"(sz));
}

__global__ void __launch_bounds__(NTHREADS, 1)
cost_volume_kernel(const float* __restrict__ x1,
                   const float* __restrict__ x2,
                   float* __restrict__ out)
{
    __shared__ __align__(16) float x2s[2][CPS][12][136];   // 52224 B
    __shared__ __align__(16) float x1s[2][CPS][TH][X1P];   // 16896 B

    const int tid  = threadIdx.x;
    const int lane = tid & 31;
    const int warp = tid >> 5;     // 0..11
    const int g    = warp >> 2;    // di-group 0..2
    const int row  = warp & 3;     // output row in tile

    const int w0 = blockIdx.x * TWt;
    const int h0 = blockIdx.y * TH;
    const int bb = blockIdx.z;

    // even-dj: [rr][e][lo/hi] f32x2 pairs on outputs (4l,4l+1)/(4l+2,4l+3)
    double accE[30];
    // odd-dj:  A = outputs (4l+1,4l+2), B = outputs (4l+3,4l+4)
    double accOA[12], accOB[12];
    // odd-dj left edge (output 4l; only lane 0's value is used)
    float  accEg[12];
#pragma unroll
    for (int i = 0; i < 30; ++i) accE[i] = 0.0;
#pragma unroll
    for (int i = 0; i < 12; ++i) { accOA[i] = 0.0; accOB[i] = 0.0; accEg[i] = 0.0f; }

    // ---------- hoisted loader state (channel-invariant) ----------
    // x2 chunks: ids [0,408) = 12 rows x 34 ; x1 chunks: ids [408,536) = 4 rows x 32
    unsigned so0, so1 = 0;
    long long go0, go1 = 0;
    bool ok0, ok1 = false, act1 = false, isx1_1 = false;
    {
        int id = tid;
        int rw = id / 34, c4 = id - rw * 34;
        int hs = h0 - 4 + rw, ws = w0 - 4 + c4 * 4;
        ok0 = ((unsigned)hs < (unsigned)Hn) && ((unsigned)ws < (unsigned)Wn);
        go0 = ok0 ? (long long)(hs * Wn + ws) * 4 : 0;
        so0 = (unsigned)(rw * 136 + c4 * 4) * 4;

        id = tid + NTHREADS;
        if (id < 408) {
            rw = id / 34; c4 = id - rw * 34;
            hs = h0 - 4 + rw; ws = w0 - 4 + c4 * 4;
            ok1 = ((unsigned)hs < (unsigned)Hn) && ((unsigned)ws < (unsigned)Wn);
            go1 = ok1 ? (long long)(hs * Wn + ws) * 4 : 0;
            so1 = (unsigned)(rw * 136 + c4 * 4) * 4;
            act1 = true;
        } else if (id < 536) {
            int j = id - 408;
            rw = j >> 5; c4 = j & 31;
            ok1 = true;
            go1 = (long long)((h0 + rw) * Wn + w0 + c4 * 4) * 4;
            so1 = (unsigned)(rw * X1P + c4 * 4) * 4;
            act1 = true; isx1_1 = true;
        }
    }
    const char* gp0 = (const char*)(x2 + (size_t)bb * Cn * HWn) + go0;
    const char* gp1 = (const char*)((isx1_1 ? x1 : x2) + (size_t)bb * Cn * HWn) + go1;

    const unsigned rbase = (unsigned)(row + 3 * g) * 136u * 4u + (unsigned)lane * 16u;

    auto load_stage = [&](int buf) {
#pragma unroll
        for (int slot = 0; slot < CPS; ++slot) {
            char* b2 = (char*)&x2s[buf][slot][0][0];
            cp16(b2 + so0, gp0, ok0);
            gp0 += (size_t)HWn * 4;
            if (act1) {
                char* d1 = (isx1_1 ? (char*)&x1s[buf][slot][0][0] : b2) + so1;
                cp16(d1, gp1, ok1);
            }
            gp1 += (size_t)HWn * 4;
        }
        asm volatile("cp.async.commit_group;");
    };

    load_stage(0);

#pragma unroll 1
    for (int t = 0; t < NSTG; ++t) {
        const int buf = t & 1;
        asm volatile("cp.async.wait_group 0;");
        __syncthreads();                 // data ready + prior buffer reads done
        if (t + 1 < NSTG) load_stage(buf ^ 1);   // overlaps this stage's compute

#pragma unroll
        for (int slot = 0; slot < CPS; ++slot) {
            const float* x1row = &x1s[buf][slot][row][0];
            float4 xv = *reinterpret_cast<const float4*>(x1row + 4 * lane);
            float x4e = x1row[4 * lane + 4];   // lane31 reads pad (discarded)
            double xlo = pkd(xv.x, xv.y);
            double xhi = pkd(xv.z, xv.w);
            double xoA = pkd(xv.y, xv.z);
            double xoB = pkd(xv.w, x4e);

            const char* base = (const char*)&x2s[buf][slot][0][0] + rbase;
#pragma unroll
            for (int rr = 0; rr < 3; ++rr) {
                const double2* rp = reinterpret_cast<const double2*>(base + rr * (136 * 4));
                double2 q0 = rp[0], q1 = rp[1], q2 = rp[2];
                double dd[6] = {q0.x, q0.y, q1.x, q1.y, q2.x, q2.y};
                // even dj: x2 pairs d[e], d[e+1]
#pragma unroll
                for (int e = 0; e < 5; ++e) {
                    fma2(accE[(rr * 5 + e) * 2 + 0], xlo, dd[e]);
                    fma2(accE[(rr * 5 + e) * 2 + 1], xhi, dd[e + 1]);
                }
                // odd dj (dj = 2o-3): shifted output pairs, aligned x2 pairs
#pragma unroll
                for (int o = 0; o < 4; ++o) {
                    fma2(accOA[rr * 4 + o], xoA, dd[o + 1]);
                    fma2(accOB[rr * 4 + o], xoB, dd[o + 2]);
                    accEg[rr * 4 + o] = fmaf(xv.x, dhi(dd[o]), accEg[rr * 4 + o]);
                }
            }
        }
    }

    // ---------- epilogue: scale + scatter ----------
    const float inv = 1.0f / 81.0f;
    const int h = h0 + row;
    const int di0 = 3 * g - 4;
#pragma unroll
    for (int rr = 0; rr < 3; ++rr) {
        // even dj
#pragma unroll
        for (int e = 0; e < 5; ++e) {
            const int djv = 2 * e - 4;
            const int tt = 9 * (di0 + rr) + djv;
            const int k = (81 - tt) % 81;
            double alo = accE[(rr * 5 + e) * 2 + 0];
            double ahi = accE[(rr * 5 + e) * 2 + 1];
            float4 o = make_float4(dlo(alo) * inv, dhi(alo) * inv,
                                   dlo(ahi) * inv, dhi(ahi) * inv);
            float* dst = out + (((size_t)(bb * Dn + k) * Hn + h) * Wn + w0 + lane * 4);
            *reinterpret_cast<float4*>(dst) = o;
        }
        // odd dj: reassemble aligned quads via shfl
#pragma unroll
        for (int o = 0; o < 4; ++o) {
            const int djv = 2 * o - 3;
            const int tt = 9 * (di0 + rr) + djv;
            const int k = (81 - tt) % 81;
            float pAl = dlo(accOA[rr * 4 + o]), pAh = dhi(accOA[rr * 4 + o]);
            float pBl = dlo(accOB[rr * 4 + o]), pBh = dhi(accOB[rr * 4 + o]);
            float f0 = __shfl_up_sync(0xffffffffu, pBh, 1);
            if (lane == 0) f0 = accEg[rr * 4 + o];
            float4 ov = make_float4(f0 * inv, pAl * inv, pAh * inv, pBl * inv);
            float* dst = out + (((size_t)(bb * Dn + k) * Hn + h) * Wn + w0 + lane * 4);
            *reinterpret_cast<float4*>(dst) = ov;
        }
    }
}

extern "C" void kernel_launch(void* const* d_in, const int* in_sizes, int n_in,
                              void* d_out, int out_size) {
    const float* x1 = (const float*)d_in[0];
    const float* x2 = (const float*)d_in[1];
    float* out = (float*)d_out;
    dim3 grid(Wn / TWt, Hn / TH, Bn);   // (2, 32, 4) = 256 blocks
    cost_volume_kernel<<<grid, NTHREADS>>>(x1, x2, out);
}

// round 9
// speedup vs baseline: 1.0927x; 1.0927x over previous
#include <cuda_runtime.h>
#include <cstdint>
#include <cstddef>

// Problem constants
#define Bn 4
#define Cn 128
#define Hn 128
#define Wn 256
#define Dn 81
#define HWn (Hn * Wn)
#define TH 4        // output rows per block
#define TWt 128     // output cols per block
#define NTHREADS 128   // 4 warps; block handles 3 di values (by blockIdx.z%3)
#define CPS 2       // channels per pipeline stage
#define NSTG (Cn / CPS)
#define X2R 6       // x2 tile rows per block (4 output rows + 2 di spread)

// pack two ADJACENT float regs into an f32x2 operand
__device__ __forceinline__ double pkd(float a, float b) {
    double d;
    asm("mov.b64 %0, {%1, %2};" : "=d"(d) : "f"(a), "f"(b));
    return d;
}
__device__ __forceinline__ void fma2(double &d, double a, double b) {
    asm("fma.rn.f32x2 %0, %1, %2, %0;" : "+d"(d) : "d"(a), "d"(b));
}
__device__ __forceinline__ float dlo(double d) { return __int_as_float(__double2loint(d)); }
__device__ __forceinline__ float dhi(double d) { return __int_as_float(__double2hiint(d)); }
// cp.async 16B; src_sz=0 -> writes 16 zero bytes (halo fill)
__device__ __forceinline__ void cp16(void* dst_smem, const void* src, bool ok) {
    unsigned dst = (unsigned)__cvta_generic_to_shared(dst_smem);
    int sz = ok ? 16 : 0;
    asm volatile("cp.async.ca.shared.global [%0], [%1], 16, %2;" :: "r"(dst), "l"(src), "r"(sz));
}

__global__ void __launch_bounds__(NTHREADS, 3)
cost_volume_kernel(const float* __restrict__ x1,
                   const float* __restrict__ x2,
                   float* __restrict__ out)
{
    // per-block x2 tile: rows (h0+3m-4) .. (h0+3m+1), 6 x 136; double buffered
    __shared__ __align__(16) float x2s[2][CPS][X2R][136];  // 13056 B
    __shared__ __align__(16) float x1s[2][CPS][TH][TWt];   //  4096 B

    const int tid  = threadIdx.x;
    const int lane = tid & 31;
    const int row  = tid >> 5;         // warp = output row 0..3

    const int w0 = blockIdx.x * TWt;
    const int h0 = blockIdx.y * TH;
    const int m  = blockIdx.z % 3;     // di-group: di = 3m-4+rr
    const int bb = blockIdx.z / 3;
    const int hr0 = h0 + 3 * m - 4;    // first x2 tile row

    // even-dj accumulators: [rr][e][lo/hi] f32x2; odd-dj scalars
    double accE[30];
    float  accO[48];
#pragma unroll
    for (int i = 0; i < 30; ++i) accE[i] = 0.0;
#pragma unroll
    for (int i = 0; i < 48; ++i) accO[i] = 0.0f;

    // ---------- hoisted loader state: 3 chunk slots ----------
    // x2 chunks ids [0,204) = 6 rows x 34; x1 chunks ids [204,332) = 4 rows x 32
    unsigned  so[3];
    long long gofs[3];
    bool okf[3], act[3], sx1[3];
#pragma unroll
    for (int s = 0; s < 3; ++s) {
        int id = tid + s * NTHREADS;
        act[s] = false; okf[s] = false; sx1[s] = false; so[s] = 0; gofs[s] = 0;
        if (id < 204) {
            int rw = id / 34, c4 = id - rw * 34;
            int hs = hr0 + rw, ws = w0 - 4 + c4 * 4;
            okf[s] = ((unsigned)hs < (unsigned)Hn) && ((unsigned)ws < (unsigned)Wn);
            gofs[s] = okf[s] ? (long long)(hs * Wn + ws) * 4 : 0;
            so[s] = (unsigned)(rw * 136 + c4 * 4) * 4;
            act[s] = true;
        } else if (id < 332) {
            int j = id - 204;
            int rw = j >> 5, c4 = j & 31;
            okf[s] = true; sx1[s] = true;
            gofs[s] = (long long)((h0 + rw) * Wn + w0 + c4 * 4) * 4;
            so[s] = (unsigned)(rw * TWt + c4 * 4) * 4;
            act[s] = true;
        }
    }
    const char* gp[3];
#pragma unroll
    for (int s = 0; s < 3; ++s)
        gp[s] = (const char*)((sx1[s] ? x1 : x2) + (size_t)bb * Cn * HWn) + gofs[s];

    auto load_ch = [&](int buf, int slot) {
#pragma unroll
        for (int s = 0; s < 3; ++s) {
            if (act[s]) {
                char* dst = (sx1[s] ? (char*)&x1s[buf][slot][0][0]
                                    : (char*)&x2s[buf][slot][0][0]) + so[s];
                cp16(dst, gp[s], okf[s]);
                gp[s] += (size_t)HWn * 4;
            }
        }
    };

    load_ch(0, 0);
    load_ch(0, 1);
    asm volatile("cp.async.commit_group;");

#pragma unroll 1
    for (int t = 0; t < NSTG; ++t) {
        const int buf = t & 1;
        if (t + 1 < NSTG) {
            load_ch(buf ^ 1, 0);
            load_ch(buf ^ 1, 1);
            asm volatile("cp.async.commit_group;");
            asm volatile("cp.async.wait_group 1;");
        } else {
            asm volatile("cp.async.wait_group 0;");
        }
        __syncthreads();

#pragma unroll
        for (int slot = 0; slot < CPS; ++slot) {
            const float4* xr = reinterpret_cast<const float4*>(&x1s[buf][slot][row][0]);
            float4 xv = xr[lane];
            float xs[4] = {xv.x, xv.y, xv.z, xv.w};
            double xlo = pkd(xv.x, xv.y);
            double xhi = pkd(xv.z, xv.w);

            const char* base = (const char*)&x2s[buf][slot][0][0]
                             + (unsigned)row * (136u * 4u) + (unsigned)lane * 16u;
#pragma unroll
            for (int rr = 0; rr < 3; ++rr) {
                // tile row = row + rr
                const float4* rp = reinterpret_cast<const float4*>(base + rr * (136 * 4));
                float4 q0 = rp[0], q1 = rp[1], q2 = rp[2];
                float v[12] = {q0.x, q0.y, q0.z, q0.w,
                               q1.x, q1.y, q1.z, q1.w,
                               q2.x, q2.y, q2.z, q2.w};
#pragma unroll
                for (int e = 0; e < 5; ++e) {
                    const int dj = 2 * e;
                    fma2(accE[(rr * 5 + e) * 2 + 0], xlo, pkd(v[dj],     v[dj + 1]));
                    fma2(accE[(rr * 5 + e) * 2 + 1], xhi, pkd(v[dj + 2], v[dj + 3]));
                }
#pragma unroll
                for (int o = 0; o < 4; ++o) {
                    const int dj = 2 * o + 1;
#pragma unroll
                    for (int p = 0; p < 4; ++p)
                        accO[(rr * 4 + o) * 4 + p] =
                            fmaf(xs[p], v[dj + p], accO[(rr * 4 + o) * 4 + p]);
                }
            }
        }
        __syncthreads();
    }

    // ---------- epilogue: scale + scatter ----------
    const float inv = 1.0f / 81.0f;
    const int h = h0 + row;
    const int di0 = 3 * m - 4;
#pragma unroll
    for (int rr = 0; rr < 3; ++rr) {
#pragma unroll
        for (int e = 0; e < 5; ++e) {
            const int djv = 2 * e - 4;
            const int tt = 9 * (di0 + rr) + djv;
            const int k = (81 - tt) % 81;
            double alo = accE[(rr * 5 + e) * 2 + 0];
            double ahi = accE[(rr * 5 + e) * 2 + 1];
            float4 o = make_float4(dlo(alo) * inv, dhi(alo) * inv,
                                   dlo(ahi) * inv, dhi(ahi) * inv);
            float* dst = out + (((size_t)(bb * Dn + k) * Hn + h) * Wn + w0 + lane * 4);
            *reinterpret_cast<float4*>(dst) = o;
        }
#pragma unroll
        for (int oj = 0; oj < 4; ++oj) {
            const int djv = 2 * oj - 3;
            const int tt = 9 * (di0 + rr) + djv;
            const int k = (81 - tt) % 81;
            float4 o;
            o.x = accO[(rr * 4 + oj) * 4 + 0] * inv;
            o.y = accO[(rr * 4 + oj) * 4 + 1] * inv;
            o.z = accO[(rr * 4 + oj) * 4 + 2] * inv;
            o.w = accO[(rr * 4 + oj) * 4 + 3] * inv;
            float* dst = out + (((size_t)(bb * Dn + k) * Hn + h) * Wn + w0 + lane * 4);
            *reinterpret_cast<float4*>(dst) = o;
        }
    }
}

extern "C" void kernel_launch(void* const* d_in, const int* in_sizes, int n_in,
                              void* d_out, int out_size) {
    const float* x1 = (const float*)d_in[0];
    const float* x2 = (const float*)d_in[1];
    float* out = (float*)d_out;
    dim3 grid(Wn / TWt, Hn / TH, Bn * 3);   // (2, 32, 12) = 768 blocks
    cost_volume_kernel<<<grid, NTHREADS>>>(x1, x2, out);
}